// round 10
// baseline (speedup 1.0000x reference)
#include <cuda_runtime.h>
#include <cuda_fp16.h>
#include <mma.h>

using namespace nvcuda;

#define NN 100000
#define NE 1600000
#define NF 64
#define NC 32
#define OS_LD 68   // float smem epilogue row stride

// ---------------- scratch (static device memory) --------------------------
__device__ __align__(256) __half2 g_x16[NN * (NF / 2)];   // prescaled x (fp16)
__device__ __align__(256) __half2 g_h1[NN * (NF / 2)];    // layer-1 output (fp16)
__device__ __align__(256) __half2 g_t3[NN * (NC / 2)];    // W3-transformed h2 (fp16)
__device__ int   g_deg_out[NN];            // zero-init; re-zeroed inside scan1
__device__ int   g_deg_in[NN];             // re-zeroed inside scan3
__device__ float g_norm_out[NN];
__device__ float g_norm_in[NN];
__device__ int   g_row_ptr[NN + 1];
__device__ int   g_partials[64];
__device__ __align__(256) int g_edge_src[NE];
__device__ __align__(256) int g_rank[NE];   // within-dst-segment rank of each edge

// ---------------- degree histograms (split; 4 edges/thread) ---------------
// hist_in also records each edge's rank (return value of the atomic).
__global__ void k_hist_in(const int4* __restrict__ dst4, int4* __restrict__ rank4) {
    int i = blockIdx.x * blockDim.x + threadIdx.x;
    if (i < NE / 4) {
        int4 d = dst4[i];
        int4 r;
        r.x = atomicAdd(&g_deg_in[d.x], 1);
        r.y = atomicAdd(&g_deg_in[d.y], 1);
        r.z = atomicAdd(&g_deg_in[d.z], 1);
        r.w = atomicAdd(&g_deg_in[d.w], 1);
        rank4[i] = r;
    }
}

__global__ void k_hist_out(const int4* __restrict__ src4) {
    int i = blockIdx.x * blockDim.x + threadIdx.x;
    if (i < NE / 4) {
        int4 s = src4[i];
        atomicAdd(&g_deg_out[s.x], 1); atomicAdd(&g_deg_out[s.y], 1);
        atomicAdd(&g_deg_out[s.z], 1); atomicAdd(&g_deg_out[s.w], 1);
    }
}

// ---------------- scan pass 1: norms + block sums + deg_out re-zero -------
#define SCAN_T 512
#define SCAN_I 4
#define SCAN_CHUNK (SCAN_T * SCAN_I)                     // 2048
#define SCAN_NB ((NN + SCAN_CHUNK - 1) / SCAN_CHUNK)     // 49

__global__ __launch_bounds__(SCAN_T) void k_scan1() {
    __shared__ int sm[SCAN_T];
    int tid = threadIdx.x;
    int base = blockIdx.x * SCAN_CHUNK + tid * SCAN_I;
    int s = 0;
#pragma unroll
    for (int j = 0; j < SCAN_I; j++) {
        int i = base + j;
        if (i < NN) {
            int di = g_deg_in[i];
            s += di;
            g_norm_in[i]  = rsqrtf((float)max(di, 1));
            g_norm_out[i] = rsqrtf((float)max(g_deg_out[i], 1));
            g_deg_out[i] = 0;                  // restore for next replay
        }
    }
    sm[tid] = s;
    __syncthreads();
    for (int off = SCAN_T / 2; off > 0; off >>= 1) {
        if (tid < off) sm[tid] += sm[tid + off];
        __syncthreads();
    }
    if (tid == 0) g_partials[blockIdx.x] = sm[0];
}

// ---------------- scan pass 2 (fused): partial-prefix + row_ptr + rezero --
__global__ __launch_bounds__(SCAN_T) void k_scan3() {
    __shared__ int sm[SCAN_T];
    __shared__ int pp[SCAN_NB];
    int tid = threadIdx.x;
    if (tid == 0) {
        int run = 0;
#pragma unroll
        for (int b = 0; b < SCAN_NB; b++) { pp[b] = run; run += g_partials[b]; }
        if (blockIdx.x == 0) g_row_ptr[NN] = NE;
    }
    int base = blockIdx.x * SCAN_CHUNK + tid * SCAN_I;
    int c[SCAN_I];
    int s = 0;
#pragma unroll
    for (int j = 0; j < SCAN_I; j++) {
        int i = base + j;
        c[j] = (i < NN) ? g_deg_in[i] : 0;
        if (i < NN) g_deg_in[i] = 0;           // restore for next replay
        s += c[j];
    }
    sm[tid] = s;
    __syncthreads();
    for (int off = 1; off < SCAN_T; off <<= 1) {
        int v = (tid >= off) ? sm[tid - off] : 0;
        __syncthreads();
        sm[tid] += v;
        __syncthreads();
    }
    int excl = sm[tid] - s + pp[blockIdx.x];
#pragma unroll
    for (int j = 0; j < SCAN_I; j++) {
        int i = base + j;
        if (i < NN) g_row_ptr[i] = excl;
        excl += c[j];
    }
}

// ---------------- scatter (ATOMIC-FREE: row_ptr[dst] + rank) --------------
__global__ void k_scatter(const int4* __restrict__ src4, const int4* __restrict__ dst4,
                          const int4* __restrict__ rank4) {
    int i = blockIdx.x * blockDim.x + threadIdx.x;
    if (i < NE / 4) {
        int4 s = src4[i];
        int4 d = dst4[i];
        int4 r = rank4[i];
        g_edge_src[g_row_ptr[d.x] + r.x] = s.x;
        g_edge_src[g_row_ptr[d.y] + r.y] = s.y;
        g_edge_src[g_row_ptr[d.z] + r.z] = s.z;
        g_edge_src[g_row_ptr[d.w] + r.w] = s.w;
    }
}

// ---------------- prescale: g_x16 = fp16(x * norm_out[row]) ---------------
__global__ void k_prescale(const float* __restrict__ x) {
    int i = blockIdx.x * blockDim.x + threadIdx.x;   // over NN*16 float4
    if (i < NN * (NF / 4)) {
        int row = i >> 4;
        float4 v = ((const float4*)x)[i];
        float s = g_norm_out[row];
        g_x16[i * 2]     = __floats2half2_rn(v.x * s, v.y * s);
        g_x16[i * 2 + 1] = __floats2half2_rn(v.z * s, v.w * s);
    }
}

// ---------------- vectorized gather-aggregate (4 edges per warp-LDG, -----
// 16 edges in flight). lane layout: edge slot = lane>>3, fc = (lane&7)*8.
__device__ __forceinline__ void acc_u4(const uint4& v, float acc[8]) {
    float2 f;
    f = __half22float2(*(const __half2*)&v.x); acc[0] += f.x; acc[1] += f.y;
    f = __half22float2(*(const __half2*)&v.y); acc[2] += f.x; acc[3] += f.y;
    f = __half22float2(*(const __half2*)&v.z); acc[4] += f.x; acc[5] += f.y;
    f = __half22float2(*(const __half2*)&v.w); acc[6] += f.x; acc[7] += f.y;
}

__device__ __forceinline__ void agg64_node(const __half* __restrict__ inh,
                                           int beg, int end, int sub, int fc,
                                           float acc[8]) {
#pragma unroll
    for (int q = 0; q < 8; q++) acc[q] = 0.f;
    int e = beg;
    for (; e + 15 < end; e += 16) {
        int i0 = g_edge_src[e + sub];
        int i1 = g_edge_src[e + 4 + sub];
        int i2 = g_edge_src[e + 8 + sub];
        int i3 = g_edge_src[e + 12 + sub];
        uint4 a = *(const uint4*)&inh[i0 * NF + fc];
        uint4 b = *(const uint4*)&inh[i1 * NF + fc];
        uint4 c = *(const uint4*)&inh[i2 * NF + fc];
        uint4 d = *(const uint4*)&inh[i3 * NF + fc];
        acc_u4(a, acc); acc_u4(b, acc); acc_u4(c, acc); acc_u4(d, acc);
    }
    for (; e + 7 < end; e += 8) {
        int i0 = g_edge_src[e + sub];
        int i1 = g_edge_src[e + 4 + sub];
        uint4 a = *(const uint4*)&inh[i0 * NF + fc];
        uint4 b = *(const uint4*)&inh[i1 * NF + fc];
        acc_u4(a, acc); acc_u4(b, acc);
    }
    for (; e < end; e += 4) {
        int eid = e + sub;
        uint4 v = make_uint4(0u, 0u, 0u, 0u);
        if (eid < end) {
            int s = g_edge_src[eid];
            v = *(const uint4*)&inh[s * NF + fc];
        }
        acc_u4(v, acc);
    }
#pragma unroll
    for (int q = 0; q < 8; q++) {
        acc[q] += __shfl_xor_sync(0xffffffffu, acc[q], 8);
        acc[q] += __shfl_xor_sync(0xffffffffu, acc[q], 16);
    }
}

// ---------------- fused layer 1: agg + norm_in + wmma GEMM + epilogue -----
__global__ __launch_bounds__(256) void k_layer1(const float* __restrict__ W1,
                                                const float* __restrict__ b1) {
    __shared__ __align__(16) __half Wh[NF * NF];       // W1 fp16
    __shared__ __align__(16) __half Ah[32][NF];        // agg tile fp16
    __shared__ __align__(16) float  Os[32][OS_LD];     // GEMM result fp32
    int tid = threadIdx.x;
    int row0 = blockIdx.x * 32;
    for (int i = tid; i < NF * NF; i += 256) Wh[i] = __float2half(W1[i]);

    const __half* inh = (const __half*)g_x16;
    int wid = tid >> 5, lane = tid & 31;
    int sub = lane >> 3;
    int fc  = (lane & 7) * 8;
#pragma unroll
    for (int j = 0; j < 4; j++) {
        int nl = (wid << 2) + j;
        int node = row0 + nl;
        float acc[8];
        agg64_node(inh, g_row_ptr[node], g_row_ptr[node + 1], sub, fc, acc);
        if (lane < 8) {
            float ni = g_norm_in[node];
#pragma unroll
            for (int q = 0; q < 8; q++) Ah[nl][fc + q] = __float2half(acc[q] * ni);
        }
    }
    __syncthreads();

    // wmma: 2x4 tiles of 16x16, one per warp, K-loop of 4
    {
        int mt = wid >> 2, nt = wid & 3;
        wmma::fragment<wmma::accumulator, 16, 16, 16, float> fC;
        wmma::fill_fragment(fC, 0.f);
#pragma unroll
        for (int k = 0; k < 4; k++) {
            wmma::fragment<wmma::matrix_a, 16, 16, 16, __half, wmma::row_major> fA;
            wmma::fragment<wmma::matrix_b, 16, 16, 16, __half, wmma::row_major> fB;
            wmma::load_matrix_sync(fA, &Ah[mt * 16][k * 16], NF);
            wmma::load_matrix_sync(fB, &Wh[(k * 16) * NF + nt * 16], NF);
            wmma::mma_sync(fC, fA, fB, fC);
        }
        wmma::store_matrix_sync(&Os[mt * 16][nt * 16], fC, OS_LD, wmma::mem_row_major);
    }
    __syncthreads();

    // epilogue: bias + relu + norm_out -> g_h1 fp16
    int er = tid >> 3;
    int ec = (tid & 7) * 8;
    int g = row0 + er;
    float so = g_norm_out[g];
#pragma unroll
    for (int q = 0; q < 8; q += 2) {
        float o0 = fmaxf(Os[er][ec + q]     + b1[ec + q],     0.f) * so;
        float o1 = fmaxf(Os[er][ec + q + 1] + b1[ec + q + 1], 0.f) * so;
        g_h1[g * 32 + ((ec + q) >> 1)] = __floats2half2_rn(o0, o1);
    }
}

// layer 2 + fused W3: t3 = (relu(aggW2+b2)*norm_out) @ W3  (all wmma) ------
__global__ __launch_bounds__(256) void k_layer2(const float* __restrict__ W2,
                                                const float* __restrict__ b2,
                                                const float* __restrict__ W3) {
    __shared__ __align__(16) __half Wh[NF * NF];       // W2 fp16
    __shared__ __align__(16) __half W3h[NF * NC];      // W3 fp16
    __shared__ __align__(16) __half Ah[32][NF];        // agg tile / h2 tile fp16
    __shared__ __align__(16) float  Os[32][OS_LD];
    int tid = threadIdx.x;
    int row0 = blockIdx.x * 32;
    for (int i = tid; i < NF * NF; i += 256) Wh[i] = __float2half(W2[i]);
    for (int i = tid; i < NF * NC; i += 256) W3h[i] = __float2half(W3[i]);

    const __half* inh = (const __half*)g_h1;
    int wid = tid >> 5, lane = tid & 31;
    int sub = lane >> 3;
    int fc  = (lane & 7) * 8;
#pragma unroll
    for (int j = 0; j < 4; j++) {
        int nl = (wid << 2) + j;
        int node = row0 + nl;
        float acc[8];
        agg64_node(inh, g_row_ptr[node], g_row_ptr[node + 1], sub, fc, acc);
        if (lane < 8) {
            float ni = g_norm_in[node];
#pragma unroll
            for (int q = 0; q < 8; q++) Ah[nl][fc + q] = __float2half(acc[q] * ni);
        }
    }
    __syncthreads();

    // GEMM 1: Os = Ah @ W2
    {
        int mt = wid >> 2, nt = wid & 3;
        wmma::fragment<wmma::accumulator, 16, 16, 16, float> fC;
        wmma::fill_fragment(fC, 0.f);
#pragma unroll
        for (int k = 0; k < 4; k++) {
            wmma::fragment<wmma::matrix_a, 16, 16, 16, __half, wmma::row_major> fA;
            wmma::fragment<wmma::matrix_b, 16, 16, 16, __half, wmma::row_major> fB;
            wmma::load_matrix_sync(fA, &Ah[mt * 16][k * 16], NF);
            wmma::load_matrix_sync(fB, &Wh[(k * 16) * NF + nt * 16], NF);
            wmma::mma_sync(fC, fA, fB, fC);
        }
        wmma::store_matrix_sync(&Os[mt * 16][nt * 16], fC, OS_LD, wmma::mem_row_major);
    }
    __syncthreads();

    // epilogue 1: h2 = relu(Os + b2) * norm_out  -> back into Ah (fp16)
    {
        int er = tid >> 3;
        int ec = (tid & 7) * 8;
        float so = g_norm_out[row0 + er];
#pragma unroll
        for (int q = 0; q < 8; q++)
            Ah[er][ec + q] = __float2half(fmaxf(Os[er][ec + q] + b2[ec + q], 0.f) * so);
    }
    __syncthreads();

    // GEMM 2: Os[:, :32] = Ah @ W3  (warps 0-3)
    if (wid < 4) {
        int mt = wid >> 1, nt = wid & 1;
        wmma::fragment<wmma::accumulator, 16, 16, 16, float> fC;
        wmma::fill_fragment(fC, 0.f);
#pragma unroll
        for (int k = 0; k < 4; k++) {
            wmma::fragment<wmma::matrix_a, 16, 16, 16, __half, wmma::row_major> fA;
            wmma::fragment<wmma::matrix_b, 16, 16, 16, __half, wmma::row_major> fB;
            wmma::load_matrix_sync(fA, &Ah[mt * 16][k * 16], NF);
            wmma::load_matrix_sync(fB, &W3h[(k * 16) * NC + nt * 16], NC);
            wmma::mma_sync(fC, fA, fB, fC);
        }
        wmma::store_matrix_sync(&Os[mt * 16][nt * 16], fC, OS_LD, wmma::mem_row_major);
    }
    __syncthreads();

    // epilogue 2: t3 fp16
    {
        int er = tid >> 3;
        int ec = (tid & 7) * 4;
        int g = row0 + er;
        g_t3[g * 16 + (ec >> 1)]     = __floats2half2_rn(Os[er][ec],     Os[er][ec + 1]);
        g_t3[g * 16 + (ec >> 1) + 1] = __floats2half2_rn(Os[er][ec + 2], Os[er][ec + 3]);
    }
}

// ---------------- final: out = norm_in * Agg(t3) + b3 ---------------------
__global__ void k_out(const float* __restrict__ b3, float* __restrict__ out) {
    int gt = blockIdx.x * blockDim.x + threadIdx.x;
    int w = gt >> 5, lane = gt & 31;
    int sub = lane >> 3;
    int fc  = (lane & 7) * 4;
    const __half* t3 = (const __half*)g_t3;
    int beg = g_row_ptr[w], end = g_row_ptr[w + 1];
    float acc[4] = {};
    int e = beg;
    for (; e + 15 < end; e += 16) {
        int i0 = g_edge_src[e + sub];
        int i1 = g_edge_src[e + 4 + sub];
        int i2 = g_edge_src[e + 8 + sub];
        int i3 = g_edge_src[e + 12 + sub];
        uint2 a = *(const uint2*)&t3[i0 * NC + fc];
        uint2 b = *(const uint2*)&t3[i1 * NC + fc];
        uint2 c = *(const uint2*)&t3[i2 * NC + fc];
        uint2 d = *(const uint2*)&t3[i3 * NC + fc];
        float2 f;
        f = __half22float2(*(const __half2*)&a.x); acc[0] += f.x; acc[1] += f.y;
        f = __half22float2(*(const __half2*)&a.y); acc[2] += f.x; acc[3] += f.y;
        f = __half22float2(*(const __half2*)&b.x); acc[0] += f.x; acc[1] += f.y;
        f = __half22float2(*(const __half2*)&b.y); acc[2] += f.x; acc[3] += f.y;
        f = __half22float2(*(const __half2*)&c.x); acc[0] += f.x; acc[1] += f.y;
        f = __half22float2(*(const __half2*)&c.y); acc[2] += f.x; acc[3] += f.y;
        f = __half22float2(*(const __half2*)&d.x); acc[0] += f.x; acc[1] += f.y;
        f = __half22float2(*(const __half2*)&d.y); acc[2] += f.x; acc[3] += f.y;
    }
    for (; e + 7 < end; e += 8) {
        int i0 = g_edge_src[e + sub];
        int i1 = g_edge_src[e + 4 + sub];
        uint2 a = *(const uint2*)&t3[i0 * NC + fc];
        uint2 b = *(const uint2*)&t3[i1 * NC + fc];
        float2 f;
        f = __half22float2(*(const __half2*)&a.x); acc[0] += f.x; acc[1] += f.y;
        f = __half22float2(*(const __half2*)&a.y); acc[2] += f.x; acc[3] += f.y;
        f = __half22float2(*(const __half2*)&b.x); acc[0] += f.x; acc[1] += f.y;
        f = __half22float2(*(const __half2*)&b.y); acc[2] += f.x; acc[3] += f.y;
    }
    for (; e < end; e += 4) {
        int eid = e + sub;
        uint2 v = make_uint2(0u, 0u);
        if (eid < end) {
            int s = g_edge_src[eid];
            v = *(const uint2*)&t3[s * NC + fc];
        }
        float2 f;
        f = __half22float2(*(const __half2*)&v.x); acc[0] += f.x; acc[1] += f.y;
        f = __half22float2(*(const __half2*)&v.y); acc[2] += f.x; acc[3] += f.y;
    }
#pragma unroll
    for (int q = 0; q < 4; q++) {
        acc[q] += __shfl_xor_sync(0xffffffffu, acc[q], 8);
        acc[q] += __shfl_xor_sync(0xffffffffu, acc[q], 16);
    }
    if (lane < 8) {
        float ni = g_norm_in[w];
        float4 bb = *(const float4*)&b3[fc];
        float4 o;
        o.x = acc[0] * ni + bb.x;
        o.y = acc[1] * ni + bb.y;
        o.z = acc[2] * ni + bb.z;
        o.w = acc[3] * ni + bb.w;
        *(float4*)&out[w * NC + fc] = o;
    }
}

// ---------------- launch -------------------------------------------------
// Fork/join on a second (non-blocking) stream; streams & events are created
// once (resource setup only — the captured work is identical every call).
extern "C" void kernel_launch(void* const* d_in, const int* in_sizes, int n_in,
                              void* d_out, int out_size) {
    const float* x   = (const float*)d_in[0];
    const int*   src = (const int*)d_in[1];
    const int*   dst = (const int*)d_in[2];
    const float* W1  = (const float*)d_in[3];
    const float* b1  = (const float*)d_in[4];
    const float* W2  = (const float*)d_in[5];
    const float* b2  = (const float*)d_in[6];
    const float* W3  = (const float*)d_in[7];
    const float* b3  = (const float*)d_in[8];
    float* out = (float*)d_out;

    static cudaStream_t s2 = nullptr;
    static cudaEvent_t evA = nullptr, evB = nullptr, evC = nullptr, evD = nullptr;
    static int* p_rank = nullptr;
    if (s2 == nullptr) {
        cudaStreamCreateWithFlags(&s2, cudaStreamNonBlocking);
        cudaEventCreateWithFlags(&evA, cudaEventDisableTiming);
        cudaEventCreateWithFlags(&evB, cudaEventDisableTiming);
        cudaEventCreateWithFlags(&evC, cudaEventDisableTiming);
        cudaEventCreateWithFlags(&evD, cudaEventDisableTiming);
        cudaGetSymbolAddress((void**)&p_rank, g_rank);
    }

    const int NB_EDGE4 = (NE / 4 + 255) / 256;          // 1563
    const int NB_PRE   = (NN * (NF / 4) + 255) / 256;   // 6250
    const int NB_OUT   = NN * 32 / 256;                 // 12500

    // fork: hist_out on s2 concurrent with hist_in on main stream
    cudaEventRecord(evA, 0);
    cudaStreamWaitEvent(s2, evA, 0);
    k_hist_out<<<NB_EDGE4, 256, 0, s2>>>((const int4*)src);
    k_hist_in<<<NB_EDGE4, 256>>>((const int4*)dst, (int4*)p_rank);
    cudaEventRecord(evB, s2);
    cudaStreamWaitEvent(0, evB, 0);

    k_scan1<<<SCAN_NB, SCAN_T>>>();

    // fork: prescale (needs only norm_out) concurrent with scan3 + scatter
    cudaEventRecord(evC, 0);
    cudaStreamWaitEvent(s2, evC, 0);
    k_prescale<<<NB_PRE, 256, 0, s2>>>(x);
    k_scan3<<<SCAN_NB, SCAN_T>>>();
    k_scatter<<<NB_EDGE4, 256>>>((const int4*)src, (const int4*)dst, (const int4*)p_rank);
    cudaEventRecord(evD, s2);
    cudaStreamWaitEvent(0, evD, 0);

    k_layer1<<<NN / 32, 256>>>(W1, b1);
    k_layer2<<<NN / 32, 256>>>(W2, b2, W3);
    k_out<<<NB_OUT, 256>>>(b3, out);
}